// round 1
// baseline (speedup 1.0000x reference)
#include <cuda_runtime.h>
#include <cstdint>

// Problem constants (match reference_code)
#define B_SZ 2
#define T_SZ 1000000
#define C_SZ 16
#define G_SZ 500000
#define K_SZ 9

// out[b, g, k, c] = textures[b, group_idx[g, k], c]
// One thread per float4 (4 channels). Layout: i = (((b*G + g)*K + k)*4 + c4).
// -> stores fully coalesced; loads: 4 lanes share one 64B texel row.
__global__ __launch_bounds__(256) void gather_groups_kernel(
    const float4* __restrict__ tex,    // [B*T*C/4] float4
    const int*    __restrict__ gidx,   // [G*K]
    float4*       __restrict__ out)    // [B*G*K*C/4]
{
    const unsigned i = blockIdx.x * 256u + threadIdx.x;   // < B*G*K*4 = 36,000,000
    const unsigned c4  = i & 3u;
    const unsigned bgk = i >> 2;                          // (b*G + g)*K + k
    const unsigned gk  = bgk % (unsigned)(G_SZ * K_SZ);
    const unsigned b   = bgk / (unsigned)(G_SZ * K_SZ);

    const int t = __ldg(&gidx[gk]);                       // broadcast across 4 lanes
    const size_t src = ((size_t)b * T_SZ + (size_t)t) * 4u + c4;  // float4 index
    const float4 v = __ldg(&tex[src]);

    // Streaming store: don't let 576MB of output writes evict the 64MB/batch
    // texture working set from L2.
    __stcs(&out[i], v);
}

extern "C" void kernel_launch(void* const* d_in, const int* in_sizes, int n_in,
                              void* d_out, int out_size) {
    // metadata order: [0] mesh_ids (unused), [1] textures f32 [B,T,C], [2] group_idx i32 [G,K]
    const float4* tex  = (const float4*)d_in[1];
    const int*    gidx = (const int*)d_in[2];
    float4*       out  = (float4*)d_out;

    const unsigned total = (unsigned)B_SZ * G_SZ * K_SZ * 4u;  // 36,000,000 float4
    const unsigned blocks = (total + 255u) / 256u;             // 140,625
    gather_groups_kernel<<<blocks, 256>>>(tex, gidx, out);
}

// round 2
// speedup vs baseline: 1.0821x; 1.0821x over previous
#include <cuda_runtime.h>
#include <cstdint>

// Problem constants (match reference_code)
#define B_SZ 2
#define T_SZ 1000000u
#define C_SZ 16
#define G_SZ 500000u
#define K_SZ 9u

// GK = 4,500,000 group-texel slots; HALF = 2,250,000
#define GK   (G_SZ * K_SZ)
#define HALF (GK / 2u)

// out[b, g, k, c] = textures[b, group_idx[g, k], c]
// Each thread serves ONE float4 channel-quad (c4) for FOUR output slots:
//   (b=0, gk0), (b=0, gk1), (b=1, gk0), (b=1, gk1)  with gk1 = gk0 + HALF.
// -> 2 independent index loads feed 4 independent texture gathers (MLP=4 on
//    the latency-critical gather path) + 4 coalesced streaming stores.
// Index traffic is read once (shared across both batches).
__global__ __launch_bounds__(256) void gather_groups_kernel(
    const float4* __restrict__ tex,    // [B*T*C/4] float4 (batch stride T*4)
    const int*    __restrict__ gidx,   // [G*K]
    float4*       __restrict__ out)    // [B*G*K*C/4] (batch stride GK*4)
{
    const unsigned i = blockIdx.x * 256u + threadIdx.x;   // < HALF*4 = 9,000,000
    if (i >= HALF * 4u) return;

    const unsigned c4  = i & 3u;
    const unsigned gk0 = i >> 2;            // [0, HALF)
    const unsigned gk1 = gk0 + HALF;        // [HALF, GK)

    // Two independent index loads
    const unsigned t0 = (unsigned)__ldg(&gidx[gk0]);
    const unsigned t1 = (unsigned)__ldg(&gidx[gk1]);

    // Four independent gathers (float4 units; batch stride = T*4)
    const unsigned s00 = t0 * 4u + c4;
    const unsigned s01 = t1 * 4u + c4;
    const unsigned s10 = T_SZ * 4u + t0 * 4u + c4;
    const unsigned s11 = T_SZ * 4u + t1 * 4u + c4;

    const float4 v00 = __ldg(&tex[s00]);
    const float4 v01 = __ldg(&tex[s01]);
    const float4 v10 = __ldg(&tex[s10]);
    const float4 v11 = __ldg(&tex[s11]);

    // Four coalesced streaming stores (keep 576MB of output out of L2)
    const unsigned o00 = gk0 * 4u + c4;
    const unsigned o01 = gk1 * 4u + c4;
    const unsigned bstr = GK * 4u;          // 18,000,000 float4 per batch
    __stcs(&out[o00],        v00);
    __stcs(&out[o01],        v01);
    __stcs(&out[o00 + bstr], v10);
    __stcs(&out[o01 + bstr], v11);
}

extern "C" void kernel_launch(void* const* d_in, const int* in_sizes, int n_in,
                              void* d_out, int out_size) {
    // metadata order: [0] mesh_ids (unused), [1] textures f32 [B,T,C], [2] group_idx i32 [G,K]
    const float4* tex  = (const float4*)d_in[1];
    const int*    gidx = (const int*)d_in[2];
    float4*       out  = (float4*)d_out;

    const unsigned total  = HALF * 4u;                 // 9,000,000 threads
    const unsigned blocks = (total + 255u) / 256u;     // 35,157
    gather_groups_kernel<<<blocks, 256>>>(tex, gidx, out);
}

// round 4
// speedup vs baseline: 1.2655x; 1.1696x over previous
#include <cuda_runtime.h>
#include <cstdint>

// Problem constants (match reference_code)
#define B_SZ 2
#define T_SZ 1000000u
#define C_SZ 16
#define G_SZ 500000u
#define K_SZ 9u

#define GK   (G_SZ * K_SZ)     // 4,500,000 slots per batch
#define QTR  (GK / 4u)         // 1,125,000
#define TPB_THREADS (GK / 2u)  // 2,250,000 threads per batch (each: 4 half-rows)

// 32B texture gather with L2 evict_last (only legal on 256-bit forms on sm_103):
// keep the 64MB/batch texture resident in L2 against the output write stream.
__device__ __forceinline__ void ldg_evict_last_32B(const void* p, unsigned long long r[4]) {
    asm("ld.global.nc.L2::evict_last.v4.b64 {%0,%1,%2,%3}, [%4];"
        : "=l"(r[0]), "=l"(r[1]), "=l"(r[2]), "=l"(r[3]) : "l"(p));
}

// 32B streaming store (evict-first): output is written once, never re-read.
__device__ __forceinline__ void stg_cs_32B(void* p, const unsigned long long r[4]) {
    asm volatile("st.global.cs.v4.b64 [%0], {%1,%2,%3,%4};"
                 :: "l"(p), "l"(r[0]), "l"(r[1]), "l"(r[2]), "l"(r[3]) : "memory");
}

// out[b, g, k, c] = textures[b, group_idx[g, k], c]
// Batch-major grid: all b=0 blocks run before b=1 blocks -> instantaneous
// texture working set = 64MB, fits L2 (126MB).
// Each thread: one 32B half-row (c8 in {0,1}) for FOUR gk slots
// (q, q+QTR, q+2QTR, q+3QTR) -> MLP=4 x 32B on the gather path.
__global__ __launch_bounds__(256) void gather_groups_kernel(
    const char* __restrict__ tex,    // [B,T,C] f32 = 64B per texel row
    const int*  __restrict__ gidx,   // [G*K]
    char*       __restrict__ out,    // [B,G,K,C] f32 = 64B per slot
    unsigned bpb)                    // blocks per batch
{
    const unsigned b = (blockIdx.x >= bpb) ? 1u : 0u;
    const unsigned i = (blockIdx.x - b * bpb) * 256u + threadIdx.x;
    if (i >= TPB_THREADS) return;

    const unsigned c8 = (i & 1u) * 32u;   // byte offset within 64B row
    const unsigned q  = i >> 1;           // [0, QTR)

    const unsigned gk0 = q;
    const unsigned gk1 = q + QTR;
    const unsigned gk2 = q + 2u * QTR;
    const unsigned gk3 = q + 3u * QTR;

    // Four independent index loads
    const unsigned t0 = (unsigned)__ldg(&gidx[gk0]);
    const unsigned t1 = (unsigned)__ldg(&gidx[gk1]);
    const unsigned t2 = (unsigned)__ldg(&gidx[gk2]);
    const unsigned t3 = (unsigned)__ldg(&gidx[gk3]);

    // Four independent 32B gathers from this batch's texture
    const char* tb = tex + (size_t)b * ((size_t)T_SZ * 64u);
    unsigned long long v0[4], v1[4], v2[4], v3[4];
    ldg_evict_last_32B(tb + (size_t)t0 * 64u + c8, v0);
    ldg_evict_last_32B(tb + (size_t)t1 * 64u + c8, v1);
    ldg_evict_last_32B(tb + (size_t)t2 * 64u + c8, v2);
    ldg_evict_last_32B(tb + (size_t)t3 * 64u + c8, v3);

    // Four coalesced 32B streaming stores
    char* ob = out + (size_t)b * ((size_t)GK * 64u);
    stg_cs_32B(ob + (size_t)gk0 * 64u + c8, v0);
    stg_cs_32B(ob + (size_t)gk1 * 64u + c8, v1);
    stg_cs_32B(ob + (size_t)gk2 * 64u + c8, v2);
    stg_cs_32B(ob + (size_t)gk3 * 64u + c8, v3);
}

extern "C" void kernel_launch(void* const* d_in, const int* in_sizes, int n_in,
                              void* d_out, int out_size) {
    // metadata order: [0] mesh_ids (unused), [1] textures f32 [B,T,C], [2] group_idx i32 [G,K]
    const char* tex  = (const char*)d_in[1];
    const int*  gidx = (const int*)d_in[2];
    char*       out  = (char*)d_out;

    const unsigned bpb    = (TPB_THREADS + 255u) / 256u;  // 8790 blocks per batch
    const unsigned blocks = bpb * 2u;                     // 17,580
    gather_groups_kernel<<<blocks, 256>>>(tex, gidx, out, bpb);
}